// round 4
// baseline (speedup 1.0000x reference)
#include <cuda_runtime.h>
#include <math.h>
#include <stdint.h>

#define BN   2
#define TT   256
#define HID  2048
#define NH   16
#define HD   128
#define BH   32
#define CS   8
#define NC   32
#define NCG  20
#define MROWS (BN*TT)

typedef unsigned long long ull;

// ------------------------- scratch (device globals) -------------------------
__device__ float g_Q[BH*TT*HD];
__device__ float g_K[BH*TT*HD];
__device__ float g_V[BH*TT*HD];
__device__ float g_Of[MROWS*HID];
__device__ float g_g[BH*TT];
__device__ float g_G[BH*TT];
__device__ float g_beta[BH*TT];
__device__ float g_Skk[BH*NC*HD*HD];
__device__ float g_Skv[BH*NC*HD*HD];

// ------------------------- helpers -------------------------
__device__ __forceinline__ float warp_sum(float v){
#pragma unroll
  for (int o = 16; o; o >>= 1) v += __shfl_xor_sync(0xffffffffu, v, o);
  return v;
}
__device__ __forceinline__ ull bcast2(float x){
  ull r; asm("mov.b64 %0, {%1, %1};" : "=l"(r) : "f"(x)); return r;
}
__device__ __forceinline__ void ffma2(ull& d, ull a, ull b){
  asm("fma.rn.f32x2 %0, %1, %2, %0;" : "+l"(d) : "l"(a), "l"(b));
}
__device__ __forceinline__ float2 unpack2(ull v){
  float2 f; asm("mov.b64 {%0, %1}, %2;" : "=f"(f.x), "=f"(f.y) : "l"(v)); return f;
}

// ------------------------- K1: gates (beta, g) -------------------------
__global__ void __launch_bounds__(256) k_gates(const float* __restrict__ x,
                                               const float* __restrict__ Wa,
                                               const float* __restrict__ ba,
                                               const float* __restrict__ Wb,
                                               const float* __restrict__ bb){
  int row = blockIdx.x;
  int b = row >> 8, t = row & 255;
  __shared__ float xr[HID];
  __shared__ float red[8][32];
  int tid = threadIdx.x;
  const float4* xp = (const float4*)(x + (size_t)row * HID);
#pragma unroll
  for (int idx = tid; idx < HID/4; idx += 256){
    float4 v = xp[idx];
    *(float4*)&xr[idx*4] = v;
  }
  __syncthreads();
  int o = tid & 31, k8 = tid >> 5;
  float partial = 0.f;
  if (o < 16){
    for (int c = k8*256; c < k8*256+256; c++) partial += xr[c] * Wa[c*NH + o];
  } else {
    int oo = o - 16;
    for (int c = k8*256; c < k8*256+256; c++) partial += xr[c] * Wb[c*NH + oo];
  }
  red[k8][o] = partial;
  __syncthreads();
  if (tid < 32){
    float v = 0.f;
#pragma unroll
    for (int u = 0; u < 8; u++) v += red[u][tid];
    if (tid < 16){
      float z = v + ba[tid];
      float ls = (z >= 0.f) ? -log1pf(expf(-z)) : (z - log1pf(expf(z)));
      g_g[(b*NH + tid)*TT + t] = ls;
    } else {
      int hh = tid - 16;
      float z = v + bb[hh];
      g_beta[(b*NH + hh)*TT + t] = 1.f / (1.f + expf(-z));
    }
  }
}

// ------------------------- K2: cumsum of g over t -------------------------
__global__ void __launch_bounds__(256) k_scanG(){
  int bh = blockIdx.x;
  int t = threadIdx.x;
  __shared__ float s[TT];
  s[t] = g_g[bh*TT + t];
  __syncthreads();
  for (int off = 1; off < TT; off <<= 1){
    float u = (t >= off) ? s[t - off] : 0.f;
    __syncthreads();
    s[t] += u;
    __syncthreads();
  }
  g_G[bh*TT + t] = s[t];
}

// ------------------------- K3: projection GEMM + SiLU (double-buffered) ------
// C[512,2048] = silu(X @ W) scattered to DST[bh][t][d]; tile 128x64.
__global__ void __launch_bounds__(256,2) k_proj(const float* __restrict__ X,
                                                const float* __restrict__ W,
                                                float* __restrict__ DST){
  __shared__ __align__(16) float As[2][16][132];
  __shared__ __align__(16) float Bs[2][16][68];
  int tid = threadIdx.x;
  int ty = tid >> 4, tx = tid & 15;
  int m0 = blockIdx.y * 128, n0 = blockIdx.x * 64;
  ull acc2[4][4];
#pragma unroll
  for (int ii = 0; ii < 4; ii++)
#pragma unroll
    for (int jj = 0; jj < 4; jj++) acc2[ii][jj] = 0ull;

  int lm = tid >> 1;            // A-load row pair
  int lc0 = (tid & 1) * 2;      // which pair of float4s
  int bk = tid >> 4, bn = tid & 15;

#define LOAD_SLAB(buf, kb) do { \
    float4 v0 = *(const float4*)&X[(size_t)(m0 + lm)*HID + (kb) + lc0*4]; \
    float4 v1 = *(const float4*)&X[(size_t)(m0 + lm)*HID + (kb) + lc0*4 + 4]; \
    As[buf][lc0*4+0][lm] = v0.x; As[buf][lc0*4+1][lm] = v0.y; \
    As[buf][lc0*4+2][lm] = v0.z; As[buf][lc0*4+3][lm] = v0.w; \
    As[buf][lc0*4+4][lm] = v1.x; As[buf][lc0*4+5][lm] = v1.y; \
    As[buf][lc0*4+6][lm] = v1.z; As[buf][lc0*4+7][lm] = v1.w; \
    float4 wv = *(const float4*)&W[(size_t)((kb) + bk)*HID + n0 + bn*4]; \
    *(float4*)&Bs[buf][bk][bn*4] = wv; \
  } while(0)

  LOAD_SLAB(0, 0);
  __syncthreads();
  for (int kb = 0; kb < HID/16; kb++){
    int cur = kb & 1;
    if (kb + 1 < HID/16) LOAD_SLAB(cur^1, (kb+1)*16);
#pragma unroll
    for (int k = 0; k < 16; k++){
      const ulonglong2* ap = (const ulonglong2*)&As[cur][k][ty*8];
      ulonglong2 aA = ap[0], aB = ap[1];
      float4 bq = *(const float4*)&Bs[cur][k][tx*4];
      ull b0 = bcast2(bq.x), b1 = bcast2(bq.y), b2 = bcast2(bq.z), b3 = bcast2(bq.w);
      ffma2(acc2[0][0], aA.x, b0); ffma2(acc2[0][1], aA.x, b1);
      ffma2(acc2[0][2], aA.x, b2); ffma2(acc2[0][3], aA.x, b3);
      ffma2(acc2[1][0], aA.y, b0); ffma2(acc2[1][1], aA.y, b1);
      ffma2(acc2[1][2], aA.y, b2); ffma2(acc2[1][3], aA.y, b3);
      ffma2(acc2[2][0], aB.x, b0); ffma2(acc2[2][1], aB.x, b1);
      ffma2(acc2[2][2], aB.x, b2); ffma2(acc2[2][3], aB.x, b3);
      ffma2(acc2[3][0], aB.y, b0); ffma2(acc2[3][1], aB.y, b1);
      ffma2(acc2[3][2], aB.y, b2); ffma2(acc2[3][3], aB.y, b3);
    }
    __syncthreads();
  }
#undef LOAD_SLAB
  int n = n0 + tx*4;
  int h = n >> 7, dd = n & 127;
#pragma unroll
  for (int m2 = 0; m2 < 4; m2++){
    float2 c0 = unpack2(acc2[m2][0]);
    float2 c1 = unpack2(acc2[m2][1]);
    float2 c2 = unpack2(acc2[m2][2]);
    float2 c3 = unpack2(acc2[m2][3]);
#pragma unroll
    for (int half = 0; half < 2; half++){
      int m = m0 + ty*8 + m2*2 + half;
      int b = m >> 8, t = m & 255;
      float z0 = half ? c0.y : c0.x;
      float z1 = half ? c1.y : c1.x;
      float z2 = half ? c2.y : c2.x;
      float z3 = half ? c3.y : c3.x;
      float4 ov;
      ov.x = z0 / (1.f + expf(-z0));
      ov.y = z1 / (1.f + expf(-z1));
      ov.z = z2 / (1.f + expf(-z2));
      ov.w = z3 / (1.f + expf(-z3));
      *(float4*)&DST[(size_t)((b*NH + h)*TT + t)*HD + dd] = ov;
    }
  }
}

// ------------------------- K4: l2 normalize q, k rows -------------------------
__global__ void __launch_bounds__(128) k_l2(){
  int row = blockIdx.x;
  float* A = blockIdx.y == 0 ? g_Q : g_K;
  int i = threadIdx.x;
  float v = A[(size_t)row*HD + i];
  float ss = warp_sum(v*v);
  __shared__ float w4[4];
  if ((i & 31) == 0) w4[i >> 5] = ss;
  __syncthreads();
  float n = sqrtf(w4[0] + w4[1] + w4[2] + w4[3]);
  A[(size_t)row*HD + i] = v / fmaxf(n, 1e-12f);
}

// ------------------------- K5: per-chunk weighted outer-product sums ----------
__global__ void __launch_bounds__(256) k_chunksum(){
  int c = blockIdx.x, bh = blockIdx.y;
  __shared__ float ks[CS*HD], vs[CS*HD], coef[CS];
  int tid = threadIdx.x;
  const float* Kb = g_K + (size_t)(bh*TT + c*CS)*HD;
  const float* Vb = g_V + (size_t)(bh*TT + c*CS)*HD;
  for (int idx = tid; idx < CS*HD; idx += 256){ ks[idx] = Kb[idx]; vs[idx] = Vb[idx]; }
  if (tid < CS){
    float Gend = g_G[bh*TT + c*CS + CS - 1];
    float Gs   = g_G[bh*TT + c*CS + tid];
    coef[tid] = g_beta[bh*TT + c*CS + tid] * expf(Gend - Gs);
  }
  __syncthreads();
  int i0 = (tid >> 4) * 8, j0 = (tid & 15) * 8;
  size_t base = ((size_t)(bh*NC + c) << 14);
  float acc[8][8];
#pragma unroll
  for (int ii = 0; ii < 8; ii++)
#pragma unroll
    for (int jj = 0; jj < 8; jj++) acc[ii][jj] = 0.f;
#pragma unroll
  for (int s = 0; s < CS; s++){
    float cj[8];
#pragma unroll
    for (int jj = 0; jj < 8; jj++) cj[jj] = ks[s*HD + j0 + jj] * coef[s];
#pragma unroll
    for (int ii = 0; ii < 8; ii++){
      float kv = ks[s*HD + i0 + ii];
#pragma unroll
      for (int jj = 0; jj < 8; jj++) acc[ii][jj] += kv * cj[jj];
    }
  }
#pragma unroll
  for (int ii = 0; ii < 8; ii++){
    *(float4*)&g_Skk[base + (size_t)(i0+ii)*HD + j0]     = *(float4*)&acc[ii][0];
    *(float4*)&g_Skk[base + (size_t)(i0+ii)*HD + j0 + 4] = *(float4*)&acc[ii][4];
  }
#pragma unroll
  for (int ii = 0; ii < 8; ii++)
#pragma unroll
    for (int jj = 0; jj < 8; jj++) acc[ii][jj] = 0.f;
#pragma unroll
  for (int s = 0; s < CS; s++){
    float cj[8];
#pragma unroll
    for (int jj = 0; jj < 8; jj++) cj[jj] = vs[s*HD + j0 + jj] * coef[s];
#pragma unroll
    for (int ii = 0; ii < 8; ii++){
      float kv = ks[s*HD + i0 + ii];
#pragma unroll
      for (int jj = 0; jj < 8; jj++) acc[ii][jj] += kv * cj[jj];
    }
  }
#pragma unroll
  for (int ii = 0; ii < 8; ii++){
    *(float4*)&g_Skv[base + (size_t)(i0+ii)*HD + j0]     = *(float4*)&acc[ii][0];
    *(float4*)&g_Skv[base + (size_t)(i0+ii)*HD + j0 + 4] = *(float4*)&acc[ii][4];
  }
}

// ------------------------- K6: scan over chunks (in place) --------------------
__global__ void __launch_bounds__(256) k_scan(){
  int bh = blockIdx.x;
  int e = blockIdx.y * 256 + threadIdx.x;
  __shared__ float dc[NC];
  if (threadIdx.x < NC){
    int c = threadIdx.x;
    dc[c] = (c == 0) ? 0.f
          : expf(g_G[bh*TT + c*CS + CS - 1] - g_G[bh*TT + (c-1)*CS + CS - 1]);
  }
  __syncthreads();
  float a = 0.f, bacc = 0.f;
#pragma unroll 4
  for (int c = 0; c < NC; c++){
    size_t off = ((size_t)(bh*NC + c) << 14) + e;
    a    = a    * dc[c] + g_Skk[off]; g_Skk[off] = a;
    bacc = bacc * dc[c] + g_Skv[off]; g_Skv[off] = bacc;
  }
}

// ------------------------- K7: batched 8-RHS CG solve + fused rms -------------
#define PHASE_A(HREG, MSM) do { \
  ull y0=0ull, y1=0ull, y2=0ull, y3=0ull; \
  _Pragma("unroll") \
  for (int jj = 0; jj < 32; jj++){ \
    const ulonglong2* pr = (const ulonglong2*)&P[qq*32+jj][0]; \
    ulonglong2 pa = pr[0], pb = pr[1]; \
    ull hb = bcast2(HREG[jj]); \
    ffma2(y0, hb, pa.x); ffma2(y1, hb, pa.y); \
    ffma2(y2, hb, pb.x); ffma2(y3, hb, pb.y); \
  } \
  ((ulonglong2*)&part[qq][i][0])[0] = make_ulonglong2(y0, y1); \
  ((ulonglong2*)&part[qq][i][0])[1] = make_ulonglong2(y2, y3); \
  { int w_ = tid >> 5, lane_ = tid & 31; \
    _Pragma("unroll") \
    for (int pp = 0; pp < 4; pp++){ \
      int idx_ = (w_ << 2) | pp; int s_ = idx_ >> 3, t_ = idx_ & 7; \
      float4 kv_ = *(const float4*)&MSM[s_][lane_*4]; \
      float4 pv_ = *(const float4*)&PT[t_][lane_*4]; \
      float pd_ = kv_.x*pv_.x + kv_.y*pv_.y + kv_.z*pv_.z + kv_.w*pv_.w; \
      pd_ = warp_sum(pd_); \
      if (lane_ == 0) dots[s_][t_] = pd_; \
    } } \
} while(0)

#define ASSEMBLE(OUTV) do { \
  float yv_[CS]; \
  _Pragma("unroll") \
  for (int q2 = 0; q2 < 4; q2++){ \
    float4 u0_ = *(const float4*)&part[q2][i][0]; \
    float4 u1_ = *(const float4*)&part[q2][i][4]; \
    if (q2 == 0){ yv_[0]=u0_.x; yv_[1]=u0_.y; yv_[2]=u0_.z; yv_[3]=u0_.w; \
                  yv_[4]=u1_.x; yv_[5]=u1_.y; yv_[6]=u1_.z; yv_[7]=u1_.w; } \
    else { yv_[0]+=u0_.x; yv_[1]+=u0_.y; yv_[2]+=u0_.z; yv_[3]+=u0_.w; \
           yv_[4]+=u1_.x; yv_[5]+=u1_.y; yv_[6]+=u1_.z; yv_[7]+=u1_.w; } \
  } \
  float ksv_[CS]; \
  _Pragma("unroll") \
  for (int s_ = 0; s_ < CS; s_++) ksv_[s_] = Ksm[s_][i]; \
  _Pragma("unroll") \
  for (int t_ = 0; t_ < CS; t_++){ \
    float a_ = cdec[t_] * yv_[t_]; \
    _Pragma("unroll") \
    for (int s_ = 0; s_ < CS; s_++) a_ += (Wc[t_][s_] * dots[s_][t_]) * ksv_[s_]; \
    OUTV[t_] = a_; \
  } \
} while(0)

__global__ void __launch_bounds__(512,1) k_solve(const float* __restrict__ lp,
                                                 const float* __restrict__ onw){
  int c = blockIdx.x, bh = blockIdx.y;
  int b = bh >> 4, h = bh & 15;
  int tid = threadIdx.x;
  int qq = tid >> 7;
  int i  = tid & 127;
  int g0 = bh*TT + c*CS;

  __shared__ __align__(16) float Ksm[CS][HD];
  __shared__ __align__(16) float Vsm[CS][HD];
  __shared__ __align__(16) float Qsm[CS][HD];
  __shared__ __align__(16) float P[HD][CS];
  __shared__ __align__(16) float PT[CS][HD+4];
  __shared__ __align__(16) float part[4][HD][CS];
  __shared__ __align__(16) float Xb[HD][CS];
  __shared__ float dots[CS][CS];
  __shared__ float Wc[CS][CS];
  __shared__ float cdec[CS];
  __shared__ float lam[HD], dg[HD];
  __shared__ float wred[4][CS];
  __shared__ float wred2[4][CS];

  {
    const float4* Ks = (const float4*)(g_K + (size_t)g0*HD);
    const float4* Vs = (const float4*)(g_V + (size_t)g0*HD);
    const float4* Qs = (const float4*)(g_Q + (size_t)g0*HD);
    for (int idx = tid; idx < CS*HD/4; idx += 512){
      ((float4*)Ksm)[idx] = Ks[idx];
      ((float4*)Vsm)[idx] = Vs[idx];
      ((float4*)Qsm)[idx] = Qs[idx];
    }
  }
  if (tid < 64){
    int t_ = tid >> 3, s_ = tid & 7;
    float w = 0.f;
    if (s_ <= t_) w = g_beta[g0 + s_] * expf(g_G[g0 + t_] - g_G[g0 + s_]);
    Wc[t_][s_] = w;
  }
  if (tid < CS){
    float Gp = (c == 0) ? 0.f : g_G[g0 - 1];
    cdec[tid] = expf(g_G[g0 + tid] - Gp);
  }
  if (tid < HD){
    float z = lp[h*HD + i];
    float sp = (z > 20.f) ? z : log1pf(expf(z));
    lam[i] = sp + 0.25f;
  }
  float hkk[32], hkv[32];
  if (c == 0){
#pragma unroll
    for (int jj = 0; jj < 32; jj++){ hkk[jj] = 0.f; hkv[jj] = 0.f; }
  } else {
    size_t base = ((size_t)(bh*NC + (c-1)) << 14) + (size_t)i*HD + qq*32;
#pragma unroll
    for (int jj = 0; jj < 32; jj += 4){
      float4 a = *(const float4*)&g_Skk[base + jj];
      hkk[jj] = a.x; hkk[jj+1] = a.y; hkk[jj+2] = a.z; hkk[jj+3] = a.w;
      float4 v = *(const float4*)&g_Skv[base + jj];
      hkv[jj] = v.x; hkv[jj+1] = v.y; hkv[jj+2] = v.z; hkv[jj+3] = v.w;
    }
  }
  if (qq == (i >> 5)) dg[i] = hkk[i & 31];
  __syncthreads();

  // ---- x0 ----
  if (tid < HD){
#pragma unroll
    for (int t = 0; t < CS; t++){
      float diag = cdec[t]*dg[i] + lam[i];
#pragma unroll
      for (int s = 0; s < CS; s++){
        float kv = Ksm[s][i];
        diag += Wc[t][s] * kv * kv;
      }
      float xv = Qsm[t][i] / (diag + 1e-8f);
      Xb[i][t] = xv; P[i][t] = xv; PT[t][i] = xv;
    }
  }
  __syncthreads();

  // ---- r0, p0, d0 ----
  float rv[CS], pv[CS], dloc[CS];
  unsigned dmask = 0;           // bit t = done flag
  PHASE_A(hkk, Ksm);
  __syncthreads();
  if (tid < HD){
    float av[CS];
    ASSEMBLE(av);
#pragma unroll
    for (int t = 0; t < CS; t++){
      float r = Qsm[t][i] - (av[t] + lam[i]*Xb[i][t]);
      rv[t] = r; pv[t] = r;
    }
    float rr[CS];
#pragma unroll
    for (int t = 0; t < CS; t++) rr[t] = warp_sum(rv[t]*rv[t]);
    if ((tid & 31) == 0){
#pragma unroll
      for (int t = 0; t < CS; t++) wred[i >> 5][t] = rr[t];
    }
#pragma unroll
    for (int t = 0; t < CS; t++){ P[i][t] = pv[t]; PT[t][i] = pv[t]; }
  }
  __syncthreads();
  if (tid < HD){
#pragma unroll
    for (int t = 0; t < CS; t++)
      dloc[t] = wred[0][t] + wred[1][t] + wred[2][t] + wred[3][t];
  }

  // ---- CG iterations (4 barriers each) ----
  for (int it = 0; it < NCG; it++){
    PHASE_A(hkk, Ksm);
    __syncthreads();
    float qv[CS];
    if (tid < HD){
      ASSEMBLE(qv);
      float pq[CS];
#pragma unroll
      for (int t = 0; t < CS; t++){
        qv[t] += lam[i] * pv[t];
        pq[t] = warp_sum(pv[t] * qv[t]);
      }
      if ((tid & 31) == 0){
#pragma unroll
        for (int t = 0; t < CS; t++) wred[i >> 5][t] = pq[t];
      }
    }
    __syncthreads();
    if (tid < HD){
      float rr[CS];
#pragma unroll
      for (int t = 0; t < CS; t++){
        float pq = wred[0][t] + wred[1][t] + wred[2][t] + wred[3][t];
        if (dloc[t] < 1e-10f) dmask |= 1u << t;
        if (fabsf(pq) < 1e-10f) dmask |= 1u << t;
        float alpha = (dmask >> t & 1u) ? 0.f : dloc[t] / pq;
        Xb[i][t] += alpha * pv[t];
        rv[t] -= alpha * qv[t];
        rr[t] = warp_sum(rv[t] * rv[t]);
      }
      if ((tid & 31) == 0){
#pragma unroll
        for (int t = 0; t < CS; t++) wred2[i >> 5][t] = rr[t];
      }
    }
    __syncthreads();
    if (tid < HD){
#pragma unroll
      for (int t = 0; t < CS; t++){
        float dn = wred2[0][t] + wred2[1][t] + wred2[2][t] + wred2[3][t];
        if (!(dmask >> t & 1u)){
          float bet = dn / dloc[t];
          dloc[t] = dn;
          pv[t] = rv[t] + bet * pv[t];
        }
        P[i][t] = pv[t]; PT[t][i] = pv[t];
      }
    }
    __syncthreads();
  }

  // ---- output: o_t = H_kv,t @ x_t, then fused rms-norm ----
  if (tid < HD){
#pragma unroll
    for (int t = 0; t < CS; t++){
      float xv = Xb[i][t];
      P[i][t] = xv; PT[t][i] = xv;
    }
  }
  __syncthreads();
  PHASE_A(hkv, Vsm);
  __syncthreads();
  float ov[CS];
  if (tid < HD){
    ASSEMBLE(ov);
    float ss[CS];
#pragma unroll
    for (int t = 0; t < CS; t++) ss[t] = warp_sum(ov[t]*ov[t]);
    if ((tid & 31) == 0){
#pragma unroll
      for (int t = 0; t < CS; t++) wred[i >> 5][t] = ss[t];
    }
  }
  __syncthreads();
  if (tid < HD){
    float wv = onw[i];
#pragma unroll
    for (int t = 0; t < CS; t++){
      float ms = (wred[0][t] + wred[1][t] + wred[2][t] + wred[3][t]) * (1.f/128.f);
      float rms = sqrtf(ms + 1e-6f);
      int ts = c*CS + t;
      g_Of[(size_t)(b*TT + ts)*HID + h*HD + i] = ov[t] / rms * wv;
    }
  }
}

// ------------------------- K9: output projection (double-buffered) ------------
__global__ void __launch_bounds__(256,2) k_out(const float* __restrict__ Wo,
                                               float* __restrict__ out){
  __shared__ __align__(16) float As[2][16][132];
  __shared__ __align__(16) float Bs[2][16][68];
  int tid = threadIdx.x;
  int ty = tid >> 4, tx = tid & 15;
  int m0 = blockIdx.y * 128, n0 = blockIdx.x * 64;
  ull acc2[4][4];
#pragma unroll
  for (int ii = 0; ii < 4; ii++)
#pragma unroll
    for (int jj = 0; jj < 4; jj++) acc2[ii][jj] = 0ull;

  int lm = tid >> 1;
  int lc0 = (tid & 1) * 2;
  int bk = tid >> 4, bn = tid & 15;

#define LOAD_SLAB(buf, kb) do { \
    float4 v0 = *(const float4*)&g_Of[(size_t)(m0 + lm)*HID + (kb) + lc0*4]; \
    float4 v1 = *(const float4*)&g_Of[(size_t)(m0 + lm)*HID + (kb) + lc0*4 + 4]; \
    As[buf][lc0*4+0][lm] = v0.x; As[buf][lc0*4+1][lm] = v0.y; \
    As[buf][lc0*4+2][lm] = v0.z; As[buf][lc0*4+3][lm] = v0.w; \
    As[buf][lc0*4+4][lm] = v1.x; As[buf][lc0*4+5][lm] = v1.y; \
    As[buf][lc0*4+6][lm] = v1.z; As[buf][lc0*4+7][lm] = v1.w; \
    float4 wv = *(const float4*)&Wo[(size_t)((kb) + bk)*HID + n0 + bn*4]; \
    *(float4*)&Bs[buf][bk][bn*4] = wv; \
  } while(0)

  LOAD_SLAB(0, 0);
  __syncthreads();
  for (int kb = 0; kb < HID/16; kb++){
    int cur = kb & 1;
    if (kb + 1 < HID/16) LOAD_SLAB(cur^1, (kb+1)*16);
#pragma unroll
    for (int k = 0; k < 16; k++){
      const ulonglong2* ap = (const ulonglong2*)&As[cur][k][ty*8];
      ulonglong2 aA = ap[0], aB = ap[1];
      float4 bq = *(const float4*)&Bs[cur][k][tx*4];
      ull b0 = bcast2(bq.x), b1 = bcast2(bq.y), b2 = bcast2(bq.z), b3 = bcast2(bq.w);
      ffma2(acc2[0][0], aA.x, b0); ffma2(acc2[0][1], aA.x, b1);
      ffma2(acc2[0][2], aA.x, b2); ffma2(acc2[0][3], aA.x, b3);
      ffma2(acc2[1][0], aA.y, b0); ffma2(acc2[1][1], aA.y, b1);
      ffma2(acc2[1][2], aA.y, b2); ffma2(acc2[1][3], aA.y, b3);
      ffma2(acc2[2][0], aB.x, b0); ffma2(acc2[2][1], aB.x, b1);
      ffma2(acc2[2][2], aB.x, b2); ffma2(acc2[2][3], aB.x, b3);
      ffma2(acc2[3][0], aB.y, b0); ffma2(acc2[3][1], aB.y, b1);
      ffma2(acc2[3][2], aB.y, b2); ffma2(acc2[3][3], aB.y, b3);
    }
    __syncthreads();
  }
#undef LOAD_SLAB
#pragma unroll
  for (int m2 = 0; m2 < 4; m2++){
    float2 c0 = unpack2(acc2[m2][0]);
    float2 c1 = unpack2(acc2[m2][1]);
    float2 c2 = unpack2(acc2[m2][2]);
    float2 c3 = unpack2(acc2[m2][3]);
    int m = m0 + ty*8 + m2*2;
    *(float4*)&out[(size_t)m*HID + n0 + tx*4]     = make_float4(c0.x, c1.x, c2.x, c3.x);
    *(float4*)&out[(size_t)(m+1)*HID + n0 + tx*4] = make_float4(c0.y, c1.y, c2.y, c3.y);
  }
}

// ------------------------- launcher -------------------------
extern "C" void kernel_launch(void* const* d_in, const int* in_sizes, int n_in,
                              void* d_out, int out_size){
  const float* x    = (const float*)d_in[0];
  const float* Wq   = (const float*)d_in[1];
  const float* Wk   = (const float*)d_in[2];
  const float* Wv   = (const float*)d_in[3];
  const float* Wa   = (const float*)d_in[4];
  const float* ba   = (const float*)d_in[5];
  const float* Wb   = (const float*)d_in[6];
  const float* bb   = (const float*)d_in[7];
  const float* lpar = (const float*)d_in[8];
  const float* onw  = (const float*)d_in[9];
  const float* Wo   = (const float*)d_in[10];
  float* out = (float*)d_out;

  float *dQ, *dK, *dV;
  cudaGetSymbolAddress((void**)&dQ, g_Q);
  cudaGetSymbolAddress((void**)&dK, g_K);
  cudaGetSymbolAddress((void**)&dV, g_V);

  k_gates<<<MROWS, 256>>>(x, Wa, ba, Wb, bb);          // launch 0
  k_scanG<<<BH, 256>>>();                              // launch 1
  k_proj<<<dim3(32, 4), 256>>>(x, Wq, dQ);             // launch 2
  k_proj<<<dim3(32, 4), 256>>>(x, Wk, dK);             // launch 3  <- profiled
  k_proj<<<dim3(32, 4), 256>>>(x, Wv, dV);             // launch 4
  k_l2<<<dim3(BH*TT, 2), 128>>>();                     // launch 5
  k_chunksum<<<dim3(NC, BH), 256>>>();                 // launch 6
  k_scan<<<dim3(BH, 64), 256>>>();                     // launch 7
  k_solve<<<dim3(NC, BH), 512>>>(lpar, onw);           // launch 8
  k_out<<<dim3(32, 4), 256>>>(Wo, out);                // launch 9
}

// round 5
// speedup vs baseline: 1.2643x; 1.2643x over previous
#include <cuda_runtime.h>
#include <math.h>
#include <stdint.h>

#define BN   2
#define TT   256
#define HID  2048
#define NOUT 2048
#define NH   16
#define HD   128
#define BH   32
#define CS   8
#define NC   32
#define NCG  16
#define MROWS (BN*TT)

typedef unsigned long long ull;

// ------------------------- scratch (device globals) -------------------------
__device__ float g_Q[BH*TT*HD];
__device__ float g_K[BH*TT*HD];
__device__ float g_V[BH*TT*HD];
__device__ float g_Of[MROWS*HID];
__device__ float g_g[BH*TT];
__device__ float g_beta[BH*TT];
__device__ float g_Skk[BH*NC*HD*HD];
__device__ float g_Skv[BH*NC*HD*HD];

// ------------------------- helpers -------------------------
__device__ __forceinline__ float warp_sum(float v){
#pragma unroll
  for (int o = 16; o; o >>= 1) v += __shfl_xor_sync(0xffffffffu, v, o);
  return v;
}
__device__ __forceinline__ float half_sum16(float v){
#pragma unroll
  for (int o = 1; o < 16; o <<= 1) v += __shfl_xor_sync(0xffffffffu, v, o);
  return v;
}
__device__ __forceinline__ ull bcast2(float x){
  ull r; asm("mov.b64 %0, {%1, %1};" : "=l"(r) : "f"(x)); return r;
}
__device__ __forceinline__ void ffma2(ull& d, ull a, ull b){
  asm("fma.rn.f32x2 %0, %1, %2, %0;" : "+l"(d) : "l"(a), "l"(b));
}
__device__ __forceinline__ float2 unpack2(ull v){
  float2 f; asm("mov.b64 {%0, %1}, %2;" : "=f"(f.x), "=f"(f.y) : "l"(v)); return f;
}
__device__ __forceinline__ float silu(float z){ return z / (1.f + expf(-z)); }

// ------------------------- K0: gates (beta, g) -------------------------
__global__ void __launch_bounds__(256) k_gates(const float* __restrict__ x,
                                               const float* __restrict__ Wa,
                                               const float* __restrict__ ba,
                                               const float* __restrict__ Wb,
                                               const float* __restrict__ bb){
  int row = blockIdx.x;
  int b = row >> 8, t = row & 255;
  __shared__ float xr[HID];
  __shared__ float red[8][32];
  int tid = threadIdx.x;
  const float4* xp = (const float4*)(x + (size_t)row * HID);
#pragma unroll
  for (int idx = tid; idx < HID/4; idx += 256){
    float4 v = xp[idx];
    *(float4*)&xr[idx*4] = v;
  }
  __syncthreads();
  int o = tid & 31, k8 = tid >> 5;
  float partial = 0.f;
  if (o < 16){
    for (int c = k8*256; c < k8*256+256; c++) partial += xr[c] * Wa[c*NH + o];
  } else {
    int oo = o - 16;
    for (int c = k8*256; c < k8*256+256; c++) partial += xr[c] * Wb[c*NH + oo];
  }
  red[k8][o] = partial;
  __syncthreads();
  if (tid < 32){
    float v = 0.f;
#pragma unroll
    for (int u = 0; u < 8; u++) v += red[u][tid];
    if (tid < 16){
      float z = v + ba[tid];
      float ls = (z >= 0.f) ? -log1pf(expf(-z)) : (z - log1pf(expf(z)));
      g_g[(b*NH + tid)*TT + t] = ls;
    } else {
      int hh = tid - 16;
      float z = v + bb[hh];
      g_beta[(b*NH + hh)*TT + t] = 1.f / (1.f + expf(-z));
    }
  }
}

// ------------------------- K1: QKV GEMM + SiLU + fused l2 ---------------------
// tile 64(M) x 128(N = one head); grid (16, 8, 3); 256 threads; microtile 4x8.
__global__ void __launch_bounds__(256,3) k_qkv(const float* __restrict__ X,
                                               const float* __restrict__ Wq,
                                               const float* __restrict__ Wk,
                                               const float* __restrict__ Wv){
  int z = blockIdx.z;
  const float* W = z == 0 ? Wq : (z == 1 ? Wk : Wv);
  float* DST     = z == 0 ? g_Q : (z == 1 ? g_K : g_V);
  __shared__ __align__(16) float As[2][16][68];
  __shared__ __align__(16) float Bs[2][16][132];
  int tid = threadIdx.x;
  int ty = tid >> 4, tx = tid & 15;
  int m0 = blockIdx.y * 64, n0 = blockIdx.x * 128;
  int h = blockIdx.x;
  ull acc2[4][4];
#pragma unroll
  for (int a = 0; a < 4; a++)
#pragma unroll
    for (int c = 0; c < 4; c++) acc2[a][c] = 0ull;

  int lm = tid >> 2, lc = tid & 3;          // A: 64 rows x 16k, 1 float4/thread
  int bk = tid >> 5, bn = (tid & 31) * 4;   // B: 16k x 128n, 2 float4/thread

#define LOAD_SLAB(buf, kb) do { \
    float4 av_ = *(const float4*)&X[(size_t)(m0 + lm)*HID + (kb) + lc*4]; \
    As[buf][lc*4+0][lm] = av_.x; As[buf][lc*4+1][lm] = av_.y; \
    As[buf][lc*4+2][lm] = av_.z; As[buf][lc*4+3][lm] = av_.w; \
    *(float4*)&Bs[buf][bk][bn]   = *(const float4*)&W[(size_t)((kb) + bk)*NOUT + n0 + bn]; \
    *(float4*)&Bs[buf][bk+8][bn] = *(const float4*)&W[(size_t)((kb) + bk + 8)*NOUT + n0 + bn]; \
  } while(0)

  LOAD_SLAB(0, 0);
  __syncthreads();
  for (int kb = 0; kb < HID/16; kb++){
    int cur = kb & 1;
    if (kb + 1 < HID/16) LOAD_SLAB(cur^1, (kb+1)*16);
#pragma unroll
    for (int k = 0; k < 16; k++){
      float4 av = *(const float4*)&As[cur][k][ty*4];
      ull a0 = bcast2(av.x), a1 = bcast2(av.y), a2 = bcast2(av.z), a3 = bcast2(av.w);
      ulonglong2 bA = *(const ulonglong2*)&Bs[cur][k][tx*8];
      ulonglong2 bB = *(const ulonglong2*)&Bs[cur][k][tx*8+4];
      ffma2(acc2[0][0], a0, bA.x); ffma2(acc2[0][1], a0, bA.y);
      ffma2(acc2[0][2], a0, bB.x); ffma2(acc2[0][3], a0, bB.y);
      ffma2(acc2[1][0], a1, bA.x); ffma2(acc2[1][1], a1, bA.y);
      ffma2(acc2[1][2], a1, bB.x); ffma2(acc2[1][3], a1, bB.y);
      ffma2(acc2[2][0], a2, bA.x); ffma2(acc2[2][1], a2, bA.y);
      ffma2(acc2[2][2], a2, bB.x); ffma2(acc2[2][3], a2, bB.y);
      ffma2(acc2[3][0], a3, bA.x); ffma2(acc2[3][1], a3, bA.y);
      ffma2(acc2[3][2], a3, bB.x); ffma2(acc2[3][3], a3, bB.y);
    }
    __syncthreads();
  }
#undef LOAD_SLAB

#pragma unroll
  for (int mi = 0; mi < 4; mi++){
    float2 p0 = unpack2(acc2[mi][0]);
    float2 p1 = unpack2(acc2[mi][1]);
    float2 p2 = unpack2(acc2[mi][2]);
    float2 p3 = unpack2(acc2[mi][3]);
    float v[8] = { silu(p0.x), silu(p0.y), silu(p1.x), silu(p1.y),
                   silu(p2.x), silu(p2.y), silu(p3.x), silu(p3.y) };
    if (z < 2){
      float s = ((v[0]*v[0]+v[1]*v[1])+(v[2]*v[2]+v[3]*v[3]))
              + ((v[4]*v[4]+v[5]*v[5])+(v[6]*v[6]+v[7]*v[7]));
      s = half_sum16(s);
      float scale = 1.f / fmaxf(sqrtf(s), 1e-12f);
#pragma unroll
      for (int u = 0; u < 8; u++) v[u] *= scale;
    }
    int m = m0 + ty*4 + mi;
    int b = m >> 8, t = m & 255;
    float* dst = &DST[(size_t)((b*NH + h)*TT + t)*HD + tx*8];
    *(float4*)dst       = make_float4(v[0], v[1], v[2], v[3]);
    *(float4*)(dst + 4) = make_float4(v[4], v[5], v[6], v[7]);
  }
}

// ------------------------- K2: chunk sums + scan fused ------------------------
// grid (8, BH), 256 threads; thread owns (row i, 8 cols) carried across all 32 chunks.
__global__ void __launch_bounds__(256,4) k_chunkscan(){
  int vslab = blockIdx.x, bh = blockIdx.y;
  int tid = threadIdx.x;
  int i  = vslab*16 + (tid >> 4);
  int j0 = (tid & 15) * 8;
  __shared__ __align__(16) float ks[CS][HD], vs[CS][HD];
  __shared__ float coef[CS];
  __shared__ float dcs;
  float ckk[8], ckv[8];
#pragma unroll
  for (int u = 0; u < 8; u++){ ckk[u] = 0.f; ckv[u] = 0.f; }

  for (int c = 0; c < NC; c++){
    if (c) __syncthreads();
    {
      const float4* Kp = (const float4*)(g_K + (size_t)(bh*TT + c*CS)*HD);
      const float4* Vp = (const float4*)(g_V + (size_t)(bh*TT + c*CS)*HD);
      ((float4*)ks)[tid] = Kp[tid];
      ((float4*)vs)[tid] = Vp[tid];
    }
    if (tid < CS){
      float s = 0.f;
      for (int u = tid + 1; u < CS; u++) s += g_g[bh*TT + c*CS + u];
      coef[tid] = g_beta[bh*TT + c*CS + tid] * expf(s);
    }
    if (tid == 8){
      float s = 0.f;
      for (int u = 0; u < CS; u++) s += g_g[bh*TT + c*CS + u];
      dcs = expf(s);
    }
    __syncthreads();
    float dc = dcs;
#pragma unroll
    for (int u = 0; u < 8; u++){ ckk[u] *= dc; ckv[u] *= dc; }
#pragma unroll
    for (int s = 0; s < CS; s++){
      float ki = ks[s][i] * coef[s];
      float4 ka = *(const float4*)&ks[s][j0];
      float4 kb = *(const float4*)&ks[s][j0+4];
      float4 va = *(const float4*)&vs[s][j0];
      float4 vb = *(const float4*)&vs[s][j0+4];
      ckk[0] += ki*ka.x; ckk[1] += ki*ka.y; ckk[2] += ki*ka.z; ckk[3] += ki*ka.w;
      ckk[4] += ki*kb.x; ckk[5] += ki*kb.y; ckk[6] += ki*kb.z; ckk[7] += ki*kb.w;
      ckv[0] += ki*va.x; ckv[1] += ki*va.y; ckv[2] += ki*va.z; ckv[3] += ki*va.w;
      ckv[4] += ki*vb.x; ckv[5] += ki*vb.y; ckv[6] += ki*vb.z; ckv[7] += ki*vb.w;
    }
    size_t base = ((size_t)(bh*NC + c) << 14) + (size_t)i*HD + j0;
    *(float4*)&g_Skk[base]   = make_float4(ckk[0], ckk[1], ckk[2], ckk[3]);
    *(float4*)&g_Skk[base+4] = make_float4(ckk[4], ckk[5], ckk[6], ckk[7]);
    *(float4*)&g_Skv[base]   = make_float4(ckv[0], ckv[1], ckv[2], ckv[3]);
    *(float4*)&g_Skv[base+4] = make_float4(ckv[4], ckv[5], ckv[6], ckv[7]);
  }
}

// ------------------------- K3: batched 8-RHS CG solve (profiled slot) ---------
// 512 threads; thread (qq = tid>>7, i = tid&127) owns H0 cols qq*32..+31 of row i
// AND the CG state for RHS t in {2qq, 2qq+1}.
#define PHASE_A(HREG, MSM) do { \
  ull y0=0ull, y1=0ull, y2=0ull, y3=0ull; \
  _Pragma("unroll") \
  for (int jj = 0; jj < 32; jj++){ \
    const ulonglong2* pr = (const ulonglong2*)&P[qq*32+jj][0]; \
    ulonglong2 pa = pr[0], pb = pr[1]; \
    ull hb = bcast2(HREG[jj]); \
    ffma2(y0, hb, pa.x); ffma2(y1, hb, pa.y); \
    ffma2(y2, hb, pb.x); ffma2(y3, hb, pb.y); \
  } \
  { float2 f0=unpack2(y0), f1=unpack2(y1), f2=unpack2(y2), f3=unpack2(y3); \
    part[qq][0][i]=f0.x; part[qq][1][i]=f0.y; part[qq][2][i]=f1.x; part[qq][3][i]=f1.y; \
    part[qq][4][i]=f2.x; part[qq][5][i]=f2.y; part[qq][6][i]=f3.x; part[qq][7][i]=f3.y; } \
  _Pragma("unroll") \
  for (int pp = 0; pp < 4; pp++){ \
    int idx_ = (warp << 2) | pp; int s_ = idx_ >> 3, t_ = idx_ & 7; \
    float4 kv_ = *(const float4*)&MSM[s_][lane*4]; \
    float4 pv_ = *(const float4*)&PT[t_][lane*4]; \
    float pd_ = kv_.x*pv_.x + kv_.y*pv_.y + kv_.z*pv_.z + kv_.w*pv_.w; \
    pd_ = warp_sum(pd_); \
    if (lane == 0) dots[s_][t_] = pd_; \
  } \
} while(0)

// assemble A*u (without lam) for the thread's 2 owned t's
#define ASM2(OUT) do { \
  _Pragma("unroll") \
  for (int u = 0; u < 2; u++){ \
    int t_ = t0 + u; \
    float y_ = part[0][t_][i] + part[1][t_][i] + part[2][t_][i] + part[3][t_][i]; \
    float a_ = cdec[t_] * y_; \
    _Pragma("unroll") \
    for (int s_ = 0; s_ < CS; s_++) a_ += (Wc[t_][s_] * dots[s_][t_]) * ksi[s_]; \
    OUT[u] = a_; \
  } \
} while(0)

__global__ void __launch_bounds__(512,1) k_solve(const float* __restrict__ lp,
                                                 const float* __restrict__ onw){
  int c = blockIdx.x, bh = blockIdx.y;
  int b = bh >> 4, h = bh & 15;
  int tid = threadIdx.x;
  int qq = tid >> 7, i = tid & 127, lane = tid & 31, warp = tid >> 5;
  int g0 = bh*TT + c*CS;
  int t0 = qq*2;

  __shared__ __align__(16) float Ksm[CS][HD], Vsm[CS][HD], Qsm[CS][HD];
  __shared__ __align__(16) float P[HD][CS];
  __shared__ __align__(16) float PT[CS][HD+4];
  __shared__ __align__(16) float part[4][CS][HD];
  __shared__ float dots[CS][CS], Wc[CS][CS], cdec[CS];
  __shared__ float lam[HD], dg[HD], gsm[CS], bsm[CS];
  __shared__ float wredA[16][2], wredB[16][2];

  // ---- loads ----
  {
    const float4* Kp = (const float4*)(g_K + (size_t)g0*HD);
    const float4* Vp = (const float4*)(g_V + (size_t)g0*HD);
    const float4* Qp = (const float4*)(g_Q + (size_t)g0*HD);
    if (tid < 256){ ((float4*)Ksm)[tid] = Kp[tid]; ((float4*)Qsm)[tid] = Qp[tid]; }
    else          { ((float4*)Vsm)[tid-256] = Vp[tid-256]; }
  }
  if (tid >= 256 && tid < 264){ gsm[tid-256] = g_g[g0 + tid-256]; bsm[tid-256] = g_beta[g0 + tid-256]; }
  if (tid >= 384 && tid < 512){
    int ii = tid - 384;
    float zz = lp[h*HD + ii];
    float sp = (zz > 20.f) ? zz : log1pf(expf(zz));
    lam[ii] = sp + 0.25f;
  }
  float hkk[32];
  if (c == 0){
#pragma unroll
    for (int jj = 0; jj < 32; jj++) hkk[jj] = 0.f;
  } else {
    size_t base = ((size_t)(bh*NC + (c-1)) << 14) + (size_t)i*HD + qq*32;
#pragma unroll
    for (int jj = 0; jj < 32; jj += 4){
      float4 a = *(const float4*)&g_Skk[base + jj];
      hkk[jj] = a.x; hkk[jj+1] = a.y; hkk[jj+2] = a.z; hkk[jj+3] = a.w;
    }
  }
  if (qq == (i >> 5)) dg[i] = hkk[i & 31];
  __syncthreads();

  // ---- coefficients (local windows of g) ----
  if (tid < 64){
    int t_ = tid >> 3, s_ = tid & 7;
    float w = 0.f;
    if (s_ <= t_){
      float s = 0.f;
      for (int u = s_+1; u <= t_; u++) s += gsm[u];
      w = bsm[s_] * expf(s);
    }
    Wc[t_][s_] = w;
  }
  if (tid >= 64 && tid < 72){
    int t_ = tid - 64;
    float s = 0.f;
    for (int u = 0; u <= t_; u++) s += gsm[u];
    cdec[t_] = expf(s);
  }
  __syncthreads();

  // ---- x0 = b / (diag(A)+lam+1e-8) ----
  float ksi[CS];
#pragma unroll
  for (int s = 0; s < CS; s++) ksi[s] = Ksm[s][i];
  float xv[2], rv[2], pv[2], dloc[2], qv[2];
  unsigned dmask = 0;
#pragma unroll
  for (int u = 0; u < 2; u++){
    int t = t0 + u;
    float diag = cdec[t]*dg[i] + lam[i];
#pragma unroll
    for (int s = 0; s < CS; s++) diag += Wc[t][s] * ksi[s] * ksi[s];
    float x = Qsm[t][i] / (diag + 1e-8f);
    xv[u] = x; P[i][t] = x; PT[t][i] = x;
  }
  __syncthreads();

  // ---- r0, p0, d0 ----
  PHASE_A(hkk, Ksm);
  __syncthreads();
  {
    float av[2];
    ASM2(av);
#pragma unroll
    for (int u = 0; u < 2; u++){
      int t = t0 + u;
      float r = Qsm[t][i] - (av[u] + lam[i]*xv[u]);
      rv[u] = r; pv[u] = r;
      float rr = warp_sum(r*r);
      if (lane == 0) wredA[warp][u] = rr;
      P[i][t] = r; PT[t][i] = r;
    }
  }
  __syncthreads();
#pragma unroll
  for (int u = 0; u < 2; u++)
    dloc[u] = wredA[qq*4][u] + wredA[qq*4+1][u] + wredA[qq*4+2][u] + wredA[qq*4+3][u];

  // ---- CG iterations ----
  for (int it = 0; it < NCG; it++){
    PHASE_A(hkk, Ksm);
    __syncthreads();
    {
      ASM2(qv);
#pragma unroll
      for (int u = 0; u < 2; u++){
        qv[u] += lam[i] * pv[u];
        float pq = warp_sum(pv[u] * qv[u]);
        if (lane == 0) wredA[warp][u] = pq;
      }
    }
    __syncthreads();
#pragma unroll
    for (int u = 0; u < 2; u++){
      float pq = wredA[qq*4][u] + wredA[qq*4+1][u] + wredA[qq*4+2][u] + wredA[qq*4+3][u];
      if (dloc[u] < 1e-10f) dmask |= 1u << u;
      if (fabsf(pq) < 1e-10f) dmask |= 1u << u;
      float alpha = (dmask >> u & 1u) ? 0.f : dloc[u] / pq;
      xv[u] += alpha * pv[u];
      rv[u] -= alpha * qv[u];
      float rr = warp_sum(rv[u] * rv[u]);
      if (lane == 0) wredB[warp][u] = rr;
    }
    __syncthreads();
#pragma unroll
    for (int u = 0; u < 2; u++){
      int t = t0 + u;
      float dn = wredB[qq*4][u] + wredB[qq*4+1][u] + wredB[qq*4+2][u] + wredB[qq*4+3][u];
      if (!(dmask >> u & 1u)){
        float bet = dn / dloc[u];
        dloc[u] = dn;
        pv[u] = rv[u] + bet * pv[u];
      }
      P[i][t] = pv[u]; PT[t][i] = pv[u];
    }
    __syncthreads();
  }

  // ---- epilogue: o_t = H_kv,t @ x_t + fused rms-norm ----
#pragma unroll
  for (int u = 0; u < 2; u++){
    int t = t0 + u;
    P[i][t] = xv[u]; PT[t][i] = xv[u];
  }
  float hkv[32];
  if (c == 0){
#pragma unroll
    for (int jj = 0; jj < 32; jj++) hkv[jj] = 0.f;
  } else {
    size_t base = ((size_t)(bh*NC + (c-1)) << 14) + (size_t)i*HD + qq*32;
#pragma unroll
    for (int jj = 0; jj < 32; jj += 4){
      float4 a = *(const float4*)&g_Skv[base + jj];
      hkv[jj] = a.x; hkv[jj+1] = a.y; hkv[jj+2] = a.z; hkv[jj+3] = a.w;
    }
  }
  __syncthreads();
  PHASE_A(hkv, Vsm);
  __syncthreads();
  float ov[2];
  ASM2(ov);
#pragma unroll
  for (int u = 0; u < 2; u++){
    float ss = warp_sum(ov[u]*ov[u]);
    if (lane == 0) wredA[warp][u] = ss;
  }
  __syncthreads();
  float wnv = onw[i];
#pragma unroll
  for (int u = 0; u < 2; u++){
    int t = t0 + u;
    float ms = (wredA[qq*4][u] + wredA[qq*4+1][u] + wredA[qq*4+2][u] + wredA[qq*4+3][u]) * (1.f/128.f);
    float rms = sqrtf(ms + 1e-6f);
    int ts = c*CS + t;
    g_Of[(size_t)(b*TT + ts)*HID + h*HD + i] = ov[u] / rms * wnv;
  }
}

// ------------------------- K4: output projection (64x64 tiles) ----------------
__global__ void __launch_bounds__(256,4) k_out(const float* __restrict__ Wo,
                                               float* __restrict__ out){
  __shared__ __align__(16) float As[2][16][68];
  __shared__ __align__(16) float Bs[2][16][68];
  int tid = threadIdx.x;
  int ty = tid >> 4, tx = tid & 15;
  int m0 = blockIdx.y * 64, n0 = blockIdx.x * 64;
  ull acc2[4][2];
#pragma unroll
  for (int a = 0; a < 4; a++){ acc2[a][0] = 0ull; acc2[a][1] = 0ull; }

  int lm = tid >> 2, lc = tid & 3;
  int bk = tid >> 4, bn = (tid & 15) * 4;

#define LOAD_SLAB(buf, kb) do { \
    float4 av_ = *(const float4*)&g_Of[(size_t)(m0 + lm)*HID + (kb) + lc*4]; \
    As[buf][lc*4+0][lm] = av_.x; As[buf][lc*4+1][lm] = av_.y; \
    As[buf][lc*4+2][lm] = av_.z; As[buf][lc*4+3][lm] = av_.w; \
    *(float4*)&Bs[buf][bk][bn] = *(const float4*)&Wo[(size_t)((kb) + bk)*HID + n0 + bn]; \
  } while(0)

  LOAD_SLAB(0, 0);
  __syncthreads();
  for (int kb = 0; kb < HID/16; kb++){
    int cur = kb & 1;
    if (kb + 1 < HID/16) LOAD_SLAB(cur^1, (kb+1)*16);
#pragma unroll
    for (int k = 0; k < 16; k++){
      float4 av = *(const float4*)&As[cur][k][ty*4];
      ull a0 = bcast2(av.x), a1 = bcast2(av.y), a2 = bcast2(av.z), a3 = bcast2(av.w);
      ulonglong2 bA = *(const ulonglong2*)&Bs[cur][k][tx*4];
      ffma2(acc2[0][0], a0, bA.x); ffma2(acc2[0][1], a0, bA.y);
      ffma2(acc2[1][0], a1, bA.x); ffma2(acc2[1][1], a1, bA.y);
      ffma2(acc2[2][0], a2, bA.x); ffma2(acc2[2][1], a2, bA.y);
      ffma2(acc2[3][0], a3, bA.x); ffma2(acc2[3][1], a3, bA.y);
    }
    __syncthreads();
  }
#undef LOAD_SLAB
#pragma unroll
  for (int mi = 0; mi < 4; mi++){
    float2 c0 = unpack2(acc2[mi][0]);
    float2 c1 = unpack2(acc2[mi][1]);
    int m = m0 + ty*4 + mi;
    *(float4*)&out[(size_t)m*HID + n0 + tx*4] = make_float4(c0.x, c0.y, c1.x, c1.y);
  }
}

// ------------------------- launcher -------------------------
extern "C" void kernel_launch(void* const* d_in, const int* in_sizes, int n_in,
                              void* d_out, int out_size){
  const float* x    = (const float*)d_in[0];
  const float* Wq   = (const float*)d_in[1];
  const float* Wk   = (const float*)d_in[2];
  const float* Wv   = (const float*)d_in[3];
  const float* Wa   = (const float*)d_in[4];
  const float* ba   = (const float*)d_in[5];
  const float* Wb   = (const float*)d_in[6];
  const float* bb   = (const float*)d_in[7];
  const float* lpar = (const float*)d_in[8];
  const float* onw  = (const float*)d_in[9];
  const float* Wo   = (const float*)d_in[10];
  float* out = (float*)d_out;

  k_gates<<<MROWS, 256>>>(x, Wa, ba, Wb, bb);          // 0
  k_qkv<<<dim3(16, 8, 3), 256>>>(x, Wq, Wk, Wv);       // 1
  k_chunkscan<<<dim3(8, BH), 256>>>();                 // 2
  k_solve<<<dim3(NC, BH), 512>>>(lpar, onw);           // 3 <- profiled
  k_out<<<dim3(32, 8), 256>>>(Wo, out);                // 4
}

// round 6
// speedup vs baseline: 1.3435x; 1.0626x over previous
#include <cuda_runtime.h>
#include <math.h>
#include <stdint.h>

#define BN   2
#define TT   256
#define HID  2048
#define NOUT 2048
#define NH   16
#define HD   128
#define BH   32
#define CS   8
#define NC   32
#define NCG  12
#define MROWS (BN*TT)

typedef unsigned long long ull;

// ------------------------- scratch (device globals) -------------------------
__device__ float g_Q[BH*TT*HD];
__device__ float g_K[BH*TT*HD];
__device__ float g_V[BH*TT*HD];
__device__ float g_Of[MROWS*HID];
__device__ float g_g[BH*TT];
__device__ float g_beta[BH*TT];
__device__ float g_Skk[BH*NC*HD*HD];
__device__ float g_Skv[BH*NC*HD*HD];

// ------------------------- helpers -------------------------
__device__ __forceinline__ float warp_sum(float v){
#pragma unroll
  for (int o = 16; o; o >>= 1) v += __shfl_xor_sync(0xffffffffu, v, o);
  return v;
}
__device__ __forceinline__ float half_sum16(float v){
#pragma unroll
  for (int o = 1; o < 16; o <<= 1) v += __shfl_xor_sync(0xffffffffu, v, o);
  return v;
}
__device__ __forceinline__ ull bcast2(float x){
  ull r; asm("mov.b64 %0, {%1, %1};" : "=l"(r) : "f"(x)); return r;
}
__device__ __forceinline__ void ffma2(ull& d, ull a, ull b){
  asm("fma.rn.f32x2 %0, %1, %2, %0;" : "+l"(d) : "l"(a), "l"(b));
}
__device__ __forceinline__ float2 unpack2(ull v){
  float2 f; asm("mov.b64 {%0, %1}, %2;" : "=f"(f.x), "=f"(f.y) : "l"(v)); return f;
}
__device__ __forceinline__ float silu(float z){ return z / (1.f + expf(-z)); }
__device__ __forceinline__ void group_bar(int qq){
  asm volatile("bar.sync %0, %1;" :: "r"(1 + qq), "r"(128) : "memory");
}

// ------------------------- K0: gates (beta, g) -------------------------
__global__ void __launch_bounds__(256) k_gates(const float* __restrict__ x,
                                               const float* __restrict__ Wa,
                                               const float* __restrict__ ba,
                                               const float* __restrict__ Wb,
                                               const float* __restrict__ bb){
  int row = blockIdx.x;
  int b = row >> 8, t = row & 255;
  __shared__ float xr[HID];
  __shared__ float red[8][32];
  int tid = threadIdx.x;
  const float4* xp = (const float4*)(x + (size_t)row * HID);
#pragma unroll
  for (int idx = tid; idx < HID/4; idx += 256){
    float4 v = xp[idx];
    *(float4*)&xr[idx*4] = v;
  }
  __syncthreads();
  int o = tid & 31, k8 = tid >> 5;
  float partial = 0.f;
  if (o < 16){
    for (int c = k8*256; c < k8*256+256; c++) partial += xr[c] * Wa[c*NH + o];
  } else {
    int oo = o - 16;
    for (int c = k8*256; c < k8*256+256; c++) partial += xr[c] * Wb[c*NH + oo];
  }
  red[k8][o] = partial;
  __syncthreads();
  if (tid < 32){
    float v = 0.f;
#pragma unroll
    for (int u = 0; u < 8; u++) v += red[u][tid];
    if (tid < 16){
      float z = v + ba[tid];
      float ls = (z >= 0.f) ? -log1pf(expf(-z)) : (z - log1pf(expf(z)));
      g_g[(b*NH + tid)*TT + t] = ls;
    } else {
      int hh = tid - 16;
      float z = v + bb[hh];
      g_beta[(b*NH + hh)*TT + t] = 1.f / (1.f + expf(-z));
    }
  }
}

// ------------------------- K1: QKV GEMM + SiLU + fused l2 ---------------------
__global__ void __launch_bounds__(256,3) k_qkv(const float* __restrict__ X,
                                               const float* __restrict__ Wq,
                                               const float* __restrict__ Wk,
                                               const float* __restrict__ Wv){
  int z = blockIdx.z;
  const float* W = z == 0 ? Wq : (z == 1 ? Wk : Wv);
  float* DST     = z == 0 ? g_Q : (z == 1 ? g_K : g_V);
  __shared__ __align__(16) float As[2][16][68];
  __shared__ __align__(16) float Bs[2][16][132];
  int tid = threadIdx.x;
  int ty = tid >> 4, tx = tid & 15;
  int m0 = blockIdx.y * 64;
  int h = blockIdx.x;
  int n0 = h * 128;
  ull acc2[4][4];
#pragma unroll
  for (int a = 0; a < 4; a++)
#pragma unroll
    for (int c = 0; c < 4; c++) acc2[a][c] = 0ull;

  int lm = tid >> 2, lc = tid & 3;
  int bk = tid >> 5, bn = (tid & 31) * 4;

#define LOAD_SLAB(buf, kb) do { \
    float4 av_ = *(const float4*)&X[(size_t)(m0 + lm)*HID + (kb) + lc*4]; \
    As[buf][lc*4+0][lm] = av_.x; As[buf][lc*4+1][lm] = av_.y; \
    As[buf][lc*4+2][lm] = av_.z; As[buf][lc*4+3][lm] = av_.w; \
    *(float4*)&Bs[buf][bk][bn]   = *(const float4*)&W[(size_t)((kb) + bk)*NOUT + n0 + bn]; \
    *(float4*)&Bs[buf][bk+8][bn] = *(const float4*)&W[(size_t)((kb) + bk + 8)*NOUT + n0 + bn]; \
  } while(0)

  LOAD_SLAB(0, 0);
  __syncthreads();
  for (int kb = 0; kb < HID/16; kb++){
    int cur = kb & 1;
    if (kb + 1 < HID/16) LOAD_SLAB(cur^1, (kb+1)*16);
#pragma unroll
    for (int k = 0; k < 16; k++){
      float4 av = *(const float4*)&As[cur][k][ty*4];
      ull a0 = bcast2(av.x), a1 = bcast2(av.y), a2 = bcast2(av.z), a3 = bcast2(av.w);
      ulonglong2 bA = *(const ulonglong2*)&Bs[cur][k][tx*8];
      ulonglong2 bB = *(const ulonglong2*)&Bs[cur][k][tx*8+4];
      ffma2(acc2[0][0], a0, bA.x); ffma2(acc2[0][1], a0, bA.y);
      ffma2(acc2[0][2], a0, bB.x); ffma2(acc2[0][3], a0, bB.y);
      ffma2(acc2[1][0], a1, bA.x); ffma2(acc2[1][1], a1, bA.y);
      ffma2(acc2[1][2], a1, bB.x); ffma2(acc2[1][3], a1, bB.y);
      ffma2(acc2[2][0], a2, bA.x); ffma2(acc2[2][1], a2, bA.y);
      ffma2(acc2[2][2], a2, bB.x); ffma2(acc2[2][3], a2, bB.y);
      ffma2(acc2[3][0], a3, bA.x); ffma2(acc2[3][1], a3, bA.y);
      ffma2(acc2[3][2], a3, bB.x); ffma2(acc2[3][3], a3, bB.y);
    }
    __syncthreads();
  }
#undef LOAD_SLAB

#pragma unroll
  for (int mi = 0; mi < 4; mi++){
    float2 p0 = unpack2(acc2[mi][0]);
    float2 p1 = unpack2(acc2[mi][1]);
    float2 p2 = unpack2(acc2[mi][2]);
    float2 p3 = unpack2(acc2[mi][3]);
    float v[8] = { silu(p0.x), silu(p0.y), silu(p1.x), silu(p1.y),
                   silu(p2.x), silu(p2.y), silu(p3.x), silu(p3.y) };
    if (z < 2){
      float s = ((v[0]*v[0]+v[1]*v[1])+(v[2]*v[2]+v[3]*v[3]))
              + ((v[4]*v[4]+v[5]*v[5])+(v[6]*v[6]+v[7]*v[7]));
      s = half_sum16(s);
      float scale = 1.f / fmaxf(sqrtf(s), 1e-12f);
#pragma unroll
      for (int u = 0; u < 8; u++) v[u] *= scale;
    }
    int m = m0 + ty*4 + mi;
    int b = m >> 8, t = m & 255;
    float* dst = &DST[(size_t)((b*NH + h)*TT + t)*HD + tx*8];
    *(float4*)dst       = make_float4(v[0], v[1], v[2], v[3]);
    *(float4*)(dst + 4) = make_float4(v[4], v[5], v[6], v[7]);
  }
}

// ------------------------- K2: chunk sums + scan fused ------------------------
__global__ void __launch_bounds__(256,4) k_chunkscan(){
  int vslab = blockIdx.x, bh = blockIdx.y;
  int tid = threadIdx.x;
  int i  = vslab*16 + (tid >> 4);
  int j0 = (tid & 15) * 8;
  __shared__ __align__(16) float ks[CS][HD], vs[CS][HD];
  __shared__ float coef[CS];
  __shared__ float dcs;
  float ckk[8], ckv[8];
#pragma unroll
  for (int u = 0; u < 8; u++){ ckk[u] = 0.f; ckv[u] = 0.f; }

  for (int c = 0; c < NC; c++){
    if (c) __syncthreads();
    {
      const float4* Kp = (const float4*)(g_K + (size_t)(bh*TT + c*CS)*HD);
      const float4* Vp = (const float4*)(g_V + (size_t)(bh*TT + c*CS)*HD);
      ((float4*)ks)[tid] = Kp[tid];
      ((float4*)vs)[tid] = Vp[tid];
    }
    if (tid < CS){
      float s = 0.f;
      for (int u = tid + 1; u < CS; u++) s += g_g[bh*TT + c*CS + u];
      coef[tid] = g_beta[bh*TT + c*CS + tid] * expf(s);
    }
    if (tid == 8){
      float s = 0.f;
      for (int u = 0; u < CS; u++) s += g_g[bh*TT + c*CS + u];
      dcs = expf(s);
    }
    __syncthreads();
    float dc = dcs;
#pragma unroll
    for (int u = 0; u < 8; u++){ ckk[u] *= dc; ckv[u] *= dc; }
#pragma unroll
    for (int s = 0; s < CS; s++){
      float ki = ks[s][i] * coef[s];
      float4 ka = *(const float4*)&ks[s][j0];
      float4 kb = *(const float4*)&ks[s][j0+4];
      float4 va = *(const float4*)&vs[s][j0];
      float4 vb = *(const float4*)&vs[s][j0+4];
      ckk[0] += ki*ka.x; ckk[1] += ki*ka.y; ckk[2] += ki*ka.z; ckk[3] += ki*ka.w;
      ckk[4] += ki*kb.x; ckk[5] += ki*kb.y; ckk[6] += ki*kb.z; ckk[7] += ki*kb.w;
      ckv[0] += ki*va.x; ckv[1] += ki*va.y; ckv[2] += ki*va.z; ckv[3] += ki*va.w;
      ckv[4] += ki*vb.x; ckv[5] += ki*vb.y; ckv[6] += ki*vb.z; ckv[7] += ki*vb.w;
    }
    size_t base = ((size_t)(bh*NC + c) << 14) + (size_t)i*HD + j0;
    *(float4*)&g_Skk[base]   = make_float4(ckk[0], ckk[1], ckk[2], ckk[3]);
    *(float4*)&g_Skk[base+4] = make_float4(ckk[4], ckk[5], ckk[6], ckk[7]);
    *(float4*)&g_Skv[base]   = make_float4(ckv[0], ckv[1], ckv[2], ckv[3]);
    *(float4*)&g_Skv[base+4] = make_float4(ckv[4], ckv[5], ckv[6], ckv[7]);
  }
}

// ------------------------- K3: batched 8-RHS CG solve -------------------------
// 512 threads; thread (qq = tid>>7, i = tid&127) owns H0 cols qq*32..+31 of row i
// and the CG state for RHS t in {2qq, 2qq+1}.
// P rows padded to 12 floats; part rows padded to 12; dots/Wc are [t][s].
#define PHASE_A(HREG, MSM) do { \
  ull y0=0ull, y1=0ull, y2=0ull, y3=0ull; \
  _Pragma("unroll") \
  for (int jj = 0; jj < 32; jj++){ \
    const ulonglong2* pr = (const ulonglong2*)&P[qq*32+jj][0]; \
    ulonglong2 pa = pr[0], pb = pr[1]; \
    ull hb = bcast2(HREG[jj]); \
    ffma2(y0, hb, pa.x); ffma2(y1, hb, pa.y); \
    ffma2(y2, hb, pb.x); ffma2(y3, hb, pb.y); \
  } \
  *(ulonglong2*)&part[qq][i][0] = make_ulonglong2(y0, y1); \
  *(ulonglong2*)&part[qq][i][4] = make_ulonglong2(y2, y3); \
  _Pragma("unroll") \
  for (int pp = 0; pp < 4; pp++){ \
    int idx_ = (warp << 2) | pp; int s_ = idx_ >> 3, t_ = idx_ & 7; \
    float4 kv_ = *(const float4*)&MSM[s_][lane*4]; \
    float4 pv_ = *(const float4*)&PT[t_][lane*4]; \
    float pd_ = kv_.x*pv_.x + kv_.y*pv_.y + kv_.z*pv_.z + kv_.w*pv_.w; \
    pd_ = warp_sum(pd_); \
    if (lane == 0) dots[t_][s_] = pd_; \
  } \
} while(0)

// assemble A*u (without lam) for the thread's 2 owned t's
#define ASM2(OUT) do { \
  float2 ya_ = make_float2(0.f, 0.f); \
  _Pragma("unroll") \
  for (int q2 = 0; q2 < 4; q2++){ \
    float2 pr_ = *(const float2*)&part[q2][i][t0]; \
    ya_.x += pr_.x; ya_.y += pr_.y; \
  } \
  _Pragma("unroll") \
  for (int u = 0; u < 2; u++){ \
    int t_ = t0 + u; \
    float a_ = cdec[t_] * (u ? ya_.y : ya_.x); \
    float4 d0_ = *(const float4*)&dots[t_][0]; \
    float4 d1_ = *(const float4*)&dots[t_][4]; \
    float4 w0_ = *(const float4*)&Wc[t_][0]; \
    float4 w1_ = *(const float4*)&Wc[t_][4]; \
    a_ += (w0_.x*d0_.x)*ksi[0] + (w0_.y*d0_.y)*ksi[1] \
        + (w0_.z*d0_.z)*ksi[2] + (w0_.w*d0_.w)*ksi[3] \
        + (w1_.x*d1_.x)*ksi[4] + (w1_.y*d1_.y)*ksi[5] \
        + (w1_.z*d1_.z)*ksi[6] + (w1_.w*d1_.w)*ksi[7]; \
    OUT[u] = a_; \
  } \
} while(0)

__global__ void __launch_bounds__(512,1) k_solve(const float* __restrict__ lp,
                                                 const float* __restrict__ onw){
  int c = blockIdx.x, bh = blockIdx.y;
  int b = bh >> 4, h = bh & 15;
  int tid = threadIdx.x;
  int qq = tid >> 7, i = tid & 127, lane = tid & 31, warp = tid >> 5;
  int g0 = bh*TT + c*CS;
  int t0 = qq*2;

  __shared__ __align__(16) float Ksm[CS][HD], Vsm[CS][HD], Qsm[CS][HD];
  __shared__ __align__(16) float P[HD][12];
  __shared__ __align__(16) float PT[CS][HD+4];
  __shared__ __align__(16) float part[4][HD][12];
  __shared__ __align__(16) float dots[CS][CS];
  __shared__ __align__(16) float Wc[CS][CS];
  __shared__ float cdec[CS];
  __shared__ float lam[HD], dg[HD], gsm[CS], bsm[CS];
  __shared__ __align__(16) float wredA[2][16];
  __shared__ __align__(16) float wredB[2][16];

  // ---- loads ----
  {
    const float4* Kp = (const float4*)(g_K + (size_t)g0*HD);
    const float4* Vp = (const float4*)(g_V + (size_t)g0*HD);
    const float4* Qp = (const float4*)(g_Q + (size_t)g0*HD);
    if (tid < 256){ ((float4*)Ksm)[tid] = Kp[tid]; ((float4*)Qsm)[tid] = Qp[tid]; }
    else          { ((float4*)Vsm)[tid-256] = Vp[tid-256]; }
  }
  if (tid >= 256 && tid < 264){ gsm[tid-256] = g_g[g0 + tid-256]; bsm[tid-256] = g_beta[g0 + tid-256]; }
  if (tid >= 384 && tid < 512){
    int ii = tid - 384;
    float zz = lp[h*HD + ii];
    float sp = (zz > 20.f) ? zz : log1pf(expf(zz));
    lam[ii] = sp + 0.25f;
  }
  float hkk[32];
  if (c == 0){
#pragma unroll
    for (int jj = 0; jj < 32; jj++) hkk[jj] = 0.f;
  } else {
    size_t base = ((size_t)(bh*NC + (c-1)) << 14) + (size_t)i*HD + qq*32;
#pragma unroll
    for (int jj = 0; jj < 32; jj += 4){
      float4 a = *(const float4*)&g_Skk[base + jj];
      hkk[jj] = a.x; hkk[jj+1] = a.y; hkk[jj+2] = a.z; hkk[jj+3] = a.w;
    }
  }
  if (qq == (i >> 5)) dg[i] = hkk[i & 31];
  __syncthreads();

  // ---- coefficients (local windows of g) ----
  if (tid < 64){
    int t_ = tid >> 3, s_ = tid & 7;
    float w = 0.f;
    if (s_ <= t_){
      float s = 0.f;
      for (int u = s_+1; u <= t_; u++) s += gsm[u];
      w = bsm[s_] * expf(s);
    }
    Wc[t_][s_] = w;
  }
  if (tid >= 64 && tid < 72){
    int t_ = tid - 64;
    float s = 0.f;
    for (int u = 0; u <= t_; u++) s += gsm[u];
    cdec[t_] = expf(s);
  }
  __syncthreads();

  // ---- x0 = b / (diag(A)+lam+1e-8) ----
  float ksi[CS];
#pragma unroll
  for (int s = 0; s < CS; s++) ksi[s] = Ksm[s][i];
  float xv[2], rv[2], pv[2], dloc[2], qv[2];
  unsigned dmask = 0;
#pragma unroll
  for (int u = 0; u < 2; u++){
    int t = t0 + u;
    float diag = cdec[t]*dg[i] + lam[i];
#pragma unroll
    for (int s = 0; s < CS; s++) diag += Wc[t][s] * ksi[s] * ksi[s];
    float x = Qsm[t][i] / (diag + 1e-8f);
    xv[u] = x; P[i][t] = x; PT[t][i] = x;
  }
  __syncthreads();

  // ---- r0, p0, d0 ----
  PHASE_A(hkk, Ksm);
  __syncthreads();
  {
    float av[2];
    ASM2(av);
#pragma unroll
    for (int u = 0; u < 2; u++){
      int t = t0 + u;
      float r = Qsm[t][i] - (av[u] + lam[i]*xv[u]);
      rv[u] = r; pv[u] = r;
      float rr = warp_sum(r*r);
      if (lane == 0) wredA[u][warp] = rr;
      P[i][t] = r; PT[t][i] = r;
    }
  }
  group_bar(qq);
#pragma unroll
  for (int u = 0; u < 2; u++){
    float4 wv = *(const float4*)&wredA[u][qq*4];
    dloc[u] = (wv.x + wv.y) + (wv.z + wv.w);
  }
  __syncthreads();

  // ---- CG iterations ----
  for (int it = 0; it < NCG; it++){
    PHASE_A(hkk, Ksm);
    __syncthreads();
    {
      ASM2(qv);
#pragma unroll
      for (int u = 0; u < 2; u++){
        qv[u] += lam[i] * pv[u];
        float pq = warp_sum(pv[u] * qv[u]);
        if (lane == 0) wredA[u][warp] = pq;
      }
    }
    group_bar(qq);
#pragma unroll
    for (int u = 0; u < 2; u++){
      float4 wv = *(const float4*)&wredA[u][qq*4];
      float pq = (wv.x + wv.y) + (wv.z + wv.w);
      if (dloc[u] < 1e-10f) dmask |= 1u << u;
      if (fabsf(pq) < 1e-10f) dmask |= 1u << u;
      float alpha = (dmask >> u & 1u) ? 0.f : dloc[u] / pq;
      xv[u] += alpha * pv[u];
      rv[u] -= alpha * qv[u];
      float rr = warp_sum(rv[u] * rv[u]);
      if (lane == 0) wredB[u][warp] = rr;
    }
    group_bar(qq);
#pragma unroll
    for (int u = 0; u < 2; u++){
      int t = t0 + u;
      float4 wv = *(const float4*)&wredB[u][qq*4];
      float dn = (wv.x + wv.y) + (wv.z + wv.w);
      if (!(dmask >> u & 1u)){
        float bet = dn / dloc[u];
        dloc[u] = dn;
        pv[u] = rv[u] + bet * pv[u];
      }
      P[i][t] = pv[u]; PT[t][i] = pv[u];
    }
    __syncthreads();
  }

  // ---- epilogue: o_t = H_kv,t @ x_t + fused rms-norm ----
#pragma unroll
  for (int u = 0; u < 2; u++){
    int t = t0 + u;
    P[i][t] = xv[u]; PT[t][i] = xv[u];
  }
  float hkv[32];
  if (c == 0){
#pragma unroll
    for (int jj = 0; jj < 32; jj++) hkv[jj] = 0.f;
  } else {
    size_t base = ((size_t)(bh*NC + (c-1)) << 14) + (size_t)i*HD + qq*32;
#pragma unroll
    for (int jj = 0; jj < 32; jj += 4){
      float4 a = *(const float4*)&g_Skv[base + jj];
      hkv[jj] = a.x; hkv[jj+1] = a.y; hkv[jj+2] = a.z; hkv[jj+3] = a.w;
    }
  }
  __syncthreads();
  PHASE_A(hkv, Vsm);
  __syncthreads();
  float ov[2];
  ASM2(ov);
#pragma unroll
  for (int u = 0; u < 2; u++){
    float ss = warp_sum(ov[u]*ov[u]);
    if (lane == 0) wredA[u][warp] = ss;
  }
  group_bar(qq);
  float wnv = onw[i];
#pragma unroll
  for (int u = 0; u < 2; u++){
    int t = t0 + u;
    float4 wv = *(const float4*)&wredA[u][qq*4];
    float ms = ((wv.x + wv.y) + (wv.z + wv.w)) * (1.f/128.f);
    float rms = sqrtf(ms + 1e-6f);
    int ts = c*CS + t;
    g_Of[(size_t)(b*TT + ts)*HID + h*HD + i] = ov[u] / rms * wnv;
  }
}

// ------------------------- K4: output projection (64x64 tiles) ----------------
__global__ void __launch_bounds__(256,4) k_out(const float* __restrict__ Wo,
                                               float* __restrict__ out){
  __shared__ __align__(16) float As[2][16][68];
  __shared__ __align__(16) float Bs[2][16][68];
  int tid = threadIdx.x;
  int ty = tid >> 4, tx = tid & 15;
  int m0 = blockIdx.y * 64, n0 = blockIdx.x * 64;
  ull acc2[4][2];
#pragma unroll
  for (int a = 0; a < 4; a++){ acc2[a][0] = 0ull; acc2[a][1] = 0ull; }

  int lm = tid >> 2, lc = tid & 3;
  int bk = tid >> 4, bn = (tid & 15) * 4;

#define LOAD_SLAB(buf, kb) do { \
    float4 av_ = *(const float4*)&g_Of[(size_t)(m0 + lm)*HID + (kb) + lc*4]; \
    As[buf][lc*4+0][lm] = av_.x; As[buf][lc*4+1][lm] = av_.y; \
    As[buf][lc*4+2][lm] = av_.z; As[buf][lc*4+3][lm] = av_.w; \
    *(float4*)&Bs[buf][bk][bn] = *(const float4*)&Wo[(size_t)((kb) + bk)*HID + n0 + bn]; \
  } while(0)

  LOAD_SLAB(0, 0);
  __syncthreads();
  for (int kb = 0; kb < HID/16; kb++){
    int cur = kb & 1;
    if (kb + 1 < HID/16) LOAD_SLAB(cur^1, (kb+1)*16);
#pragma unroll
    for (int k = 0; k < 16; k++){
      float4 av = *(const float4*)&As[cur][k][ty*4];
      ull a0 = bcast2(av.x), a1 = bcast2(av.y), a2 = bcast2(av.z), a3 = bcast2(av.w);
      ulonglong2 bA = *(const ulonglong2*)&Bs[cur][k][tx*4];
      ffma2(acc2[0][0], a0, bA.x); ffma2(acc2[0][1], a0, bA.y);
      ffma2(acc2[1][0], a1, bA.x); ffma2(acc2[1][1], a1, bA.y);
      ffma2(acc2[2][0], a2, bA.x); ffma2(acc2[2][1], a2, bA.y);
      ffma2(acc2[3][0], a3, bA.x); ffma2(acc2[3][1], a3, bA.y);
    }
    __syncthreads();
  }
#undef LOAD_SLAB
#pragma unroll
  for (int mi = 0; mi < 4; mi++){
    float2 c0 = unpack2(acc2[mi][0]);
    float2 c1 = unpack2(acc2[mi][1]);
    int m = m0 + ty*4 + mi;
    *(float4*)&out[(size_t)m*HID + n0 + tx*4] = make_float4(c0.x, c0.y, c1.x, c1.y);
  }
}

// ------------------------- launcher -------------------------
extern "C" void kernel_launch(void* const* d_in, const int* in_sizes, int n_in,
                              void* d_out, int out_size){
  const float* x    = (const float*)d_in[0];
  const float* Wq   = (const float*)d_in[1];
  const float* Wk   = (const float*)d_in[2];
  const float* Wv   = (const float*)d_in[3];
  const float* Wa   = (const float*)d_in[4];
  const float* ba   = (const float*)d_in[5];
  const float* Wb   = (const float*)d_in[6];
  const float* bb   = (const float*)d_in[7];
  const float* lpar = (const float*)d_in[8];
  const float* onw  = (const float*)d_in[9];
  const float* Wo   = (const float*)d_in[10];
  float* out = (float*)d_out;

  k_gates<<<MROWS, 256>>>(x, Wa, ba, Wb, bb);          // 0
  k_qkv<<<dim3(16, 8, 3), 256>>>(x, Wq, Wk, Wv);       // 1
  k_chunkscan<<<dim3(8, BH), 256>>>();                 // 2
  k_solve<<<dim3(NC, BH), 512>>>(lpar, onw);           // 3 <- profiled
  k_out<<<dim3(32, 8), 256>>>(Wo, out);                // 4
}